// round 2
// baseline (speedup 1.0000x reference)
#include <cuda_runtime.h>
#include <cuda_bf16.h>

// Problem: RHS of 2-field Burgers-like PDE on nonuniform 2048x4096 grid.
// Inputs (metadata order): t[1], state[2*NX*NY], x[NX], y[NY], mu[1]
// Output: [2, NX, NY] float32.

#define NX_MAX 2048
#define NY_MAX 4096

// Coefficient scratch (allocation-free rule -> __device__ globals).
// Rows 0..2 = d1 coeffs (a,b,c), rows 3..5 = d2 coeffs (a,b,c).
__device__ float g_cx[6][NX_MAX];
__device__ float g_cy[6][NY_MAX];

__device__ __forceinline__ void stencil_coeffs(const float* __restrict__ g,
                                               int n, int k, float* c) {
    if (k == 0) {
        float hA = g[1] - g[0], hB = g[2] - g[1];
        c[0] = -(2.f * hA + hB) / (hA * (hA + hB));
        c[1] = (hA + hB) / (hA * hB);
        c[2] = -hA / (hB * (hA + hB));
        c[3] = 2.f / (hA * (hA + hB));
        c[4] = -2.f / (hA * hB);
        c[5] = 2.f / (hB * (hA + hB));
    } else if (k == n - 1) {
        float hC = g[n - 2] - g[n - 3], hD = g[n - 1] - g[n - 2];
        c[0] = hD / (hC * (hC + hD));
        c[1] = -(hC + hD) / (hC * hD);
        c[2] = (hC + 2.f * hD) / (hD * (hC + hD));
        c[3] = 2.f / (hC * (hC + hD));
        c[4] = -2.f / (hC * hD);
        c[5] = 2.f / (hD * (hC + hD));
    } else {
        float h1 = g[k] - g[k - 1], h2 = g[k + 1] - g[k];
        c[0] = -h2 / (h1 * (h1 + h2));
        c[1] = (h2 - h1) / (h1 * h2);
        c[2] = h1 / (h2 * (h1 + h2));
        c[3] = 2.f / (h1 * (h1 + h2));
        c[4] = -2.f / (h1 * h2);
        c[5] = 2.f / (h2 * (h1 + h2));
    }
}

__global__ __launch_bounds__(256)
void coeff_kernel(const float* __restrict__ x, int nx,
                  const float* __restrict__ y, int ny) {
    int k = blockIdx.x * blockDim.x + threadIdx.x;
    float c[6];
    if (k < nx) {
        stencil_coeffs(x, nx, k, c);
#pragma unroll
        for (int q = 0; q < 6; q++) g_cx[q][k] = c[q];
    }
    if (k < ny) {
        stencil_coeffs(y, ny, k, c);
#pragma unroll
        for (int q = 0; q < 6; q++) g_cy[q][k] = c[q];
    }
}

__global__ __launch_bounds__(256)
void rhs_kernel(const float* __restrict__ state,
                const float* __restrict__ mu_p,
                float* __restrict__ out, int nx, int ny) {
    int j = blockIdx.x * 32 + threadIdx.x;
    int i = blockIdx.y * 8 + threadIdx.y;
    if (i >= nx || j >= ny) return;

    const unsigned plane = (unsigned)nx * (unsigned)ny;  // 8.4M < 2^31
    const float* __restrict__ u = state;
    const float* __restrict__ v = state + plane;
    float mu = mu_p[0];

    // Clamped stencil center: boundary one-sided stencils read exactly the
    // points {0,1,2} / {n-3,n-2,n-1}, which equal the interior pattern
    // centered at the clamped index. Coefficients come pre-specialized.
    int jc = min(max(j, 1), ny - 2);
    int ic = min(max(i, 1), nx - 2);
    int cyi = j - (jc - 1);   // where (i,j) sits within the y-stencil triple

    unsigned rowi = (unsigned)i * (unsigned)ny;
    // y-direction stencil values (contiguous, coalesced)
    float uy0 = u[rowi + jc - 1], uy1 = u[rowi + jc], uy2 = u[rowi + jc + 1];
    float vy0 = v[rowi + jc - 1], vy1 = v[rowi + jc], vy2 = v[rowi + jc + 1];
    // x-direction stencil values (row-strided; reuse via L1/L2)
    unsigned rm = (unsigned)(ic - 1) * (unsigned)ny + (unsigned)j;
    unsigned r0 = (unsigned)ic * (unsigned)ny + (unsigned)j;
    unsigned rp = (unsigned)(ic + 1) * (unsigned)ny + (unsigned)j;
    float ux0 = u[rm], ux1 = u[r0], ux2 = u[rp];
    float vx0 = v[rm], vx1 = v[r0], vx2 = v[rp];

    float cy1a = g_cy[0][j], cy1b = g_cy[1][j], cy1c = g_cy[2][j];
    float cy2a = g_cy[3][j], cy2b = g_cy[4][j], cy2c = g_cy[5][j];
    float cx1a = g_cx[0][i], cx1b = g_cx[1][i], cx1c = g_cx[2][i];
    float cx2a = g_cx[3][i], cx2b = g_cx[4][i], cx2c = g_cx[5][i];

    float d1y_u = cy1a * uy0 + cy1b * uy1 + cy1c * uy2;
    float d2y_u = cy2a * uy0 + cy2b * uy1 + cy2c * uy2;
    float d1y_v = cy1a * vy0 + cy1b * vy1 + cy1c * vy2;
    float d2y_v = cy2a * vy0 + cy2b * vy1 + cy2c * vy2;

    float d1x_u = cx1a * ux0 + cx1b * ux1 + cx1c * ux2;
    float d2x_u = cx2a * ux0 + cx2b * ux1 + cx2c * ux2;
    float d1x_v = cx1a * vx0 + cx1b * vx1 + cx1c * vx2;
    float d2x_v = cx2a * vx0 + cx2b * vx1 + cx2c * vx2;

    // Center values: (i,j) is one of the three y-stencil points.
    float ucen = (cyi == 0) ? uy0 : ((cyi == 1) ? uy1 : uy2);
    float vcen = (cyi == 0) ? vy0 : ((cyi == 1) ? vy1 : vy2);

    float du = mu * (d2y_u + d2x_u) - ucen * d1x_u - vcen * d1y_u + 0.01f;
    float dv = mu * (d2y_v + d2x_v) - ucen * d1x_v - vcen * d1y_v;

    // Boundary zeroing per reference
    if (j == 0 || j == ny - 1 || i == 0) du = 0.f;
    if (j == 0 || i == 0) dv = 0.f;

    out[rowi + j] = du;
    out[plane + rowi + j] = dv;
}

extern "C" void kernel_launch(void* const* d_in, const int* in_sizes, int n_in,
                              void* d_out, int out_size) {
    const float* state = (const float*)d_in[1];
    const float* x = (const float*)d_in[2];
    const float* y = (const float*)d_in[3];
    const float* mu = (const float*)d_in[4];
    int nx = in_sizes[2];
    int ny = in_sizes[3];
    float* out = (float*)d_out;

    int nmax = nx > ny ? nx : ny;
    coeff_kernel<<<(nmax + 255) / 256, 256>>>(x, nx, y, ny);

    dim3 block(32, 8);
    dim3 grid((ny + 31) / 32, (nx + 7) / 8);
    rhs_kernel<<<grid, block>>>(state, mu, out, nx, ny);
}

// round 4
// speedup vs baseline: 1.3840x; 1.3840x over previous
#include <cuda_runtime.h>
#include <cuda_bf16.h>

// RHS of 2-field Burgers-like PDE on nonuniform 2048x4096 grid.
// Inputs (metadata order): t[1], state[2*NX*NY], x[NX], y[NY], mu[1]
// Output: [2, NX, NY] float32.

#define NX_MAX 2048
#define NY_MAX 4096
#define FULLMASK 0xffffffffu

// Packed stencil coefficients (allocation-free -> __device__ globals).
// A = (d1a, d1b, d1c, d2a), B = (d2b, d2c)
__device__ float4 g_cxA[NX_MAX];
__device__ float2 g_cxB[NX_MAX];
__device__ float4 g_cyA[NY_MAX];
__device__ float2 g_cyB[NY_MAX];

__device__ __forceinline__ void stencil_coeffs(const float* __restrict__ g,
                                               int n, int k, float* c) {
    if (k == 0) {
        float hA = g[1] - g[0], hB = g[2] - g[1];
        c[0] = -(2.f * hA + hB) / (hA * (hA + hB));
        c[1] = (hA + hB) / (hA * hB);
        c[2] = -hA / (hB * (hA + hB));
        c[3] = 2.f / (hA * (hA + hB));
        c[4] = -2.f / (hA * hB);
        c[5] = 2.f / (hB * (hA + hB));
    } else if (k == n - 1) {
        float hC = g[n - 2] - g[n - 3], hD = g[n - 1] - g[n - 2];
        c[0] = hD / (hC * (hC + hD));
        c[1] = -(hC + hD) / (hC * hD);
        c[2] = (hC + 2.f * hD) / (hD * (hC + hD));
        c[3] = 2.f / (hC * (hC + hD));
        c[4] = -2.f / (hC * hD);
        c[5] = 2.f / (hD * (hC + hD));
    } else {
        float h1 = g[k] - g[k - 1], h2 = g[k + 1] - g[k];
        c[0] = -h2 / (h1 * (h1 + h2));
        c[1] = (h2 - h1) / (h1 * h2);
        c[2] = h1 / (h2 * (h1 + h2));
        c[3] = 2.f / (h1 * (h1 + h2));
        c[4] = -2.f / (h1 * h2);
        c[5] = 2.f / (h2 * (h1 + h2));
    }
}

__global__ __launch_bounds__(256)
void coeff_kernel(const float* __restrict__ x, int nx,
                  const float* __restrict__ y, int ny) {
    int k = blockIdx.x * blockDim.x + threadIdx.x;
    float c[6];
    if (k < nx) {
        stencil_coeffs(x, nx, k, c);
        g_cxA[k] = make_float4(c[0], c[1], c[2], c[3]);
        g_cxB[k] = make_float2(c[4], c[5]);
    }
    if (k < ny) {
        stencil_coeffs(y, ny, k, c);
        g_cyA[k] = make_float4(c[0], c[1], c[2], c[3]);
        g_cyB[k] = make_float2(c[4], c[5]);
    }
}

// Warp layout: 32 lanes load columns j0-1+lane; lanes 1..30 produce outputs.
// Each thread computes 4 consecutive i-rows -> loads a 6-row column once.
__global__ __launch_bounds__(256)
void rhs_kernel(const float* __restrict__ state,
                const float* __restrict__ mu_p,
                float* __restrict__ out, int nx, int ny) {
    const int lane = threadIdx.x;
    const int j = blockIdx.x * 30 + lane - 1;          // computing j (lanes 1..30)
    const int jl = min(max(j, 0), ny - 1);             // load column (clamped)
    const int i0 = (blockIdx.y * blockDim.y + threadIdx.y) * 4;
    const unsigned plane = (unsigned)nx * (unsigned)ny;
    const float* __restrict__ u = state;
    const float* __restrict__ v = state + plane;
    const float mu = mu_p[0];

    // 6-row column of u,v at this lane's j (rows i0-1 .. i0+4, i-clamped).
    float uc[6], vc[6];
#pragma unroll
    for (int k = 0; k < 6; k++) {
        int ir = min(max(i0 - 1 + k, 0), nx - 1);
        unsigned off = (unsigned)ir * (unsigned)ny + (unsigned)jl;
        uc[k] = __ldg(u + off);
        vc[k] = __ldg(v + off);
    }

    const float4 cya = g_cyA[jl];
    const float2 cyb = g_cyB[jl];
    const bool compute = (lane >= 1 && lane <= 30 && j < ny);
    const bool yedge = (j == 0) || (j == ny - 1);
    const unsigned obase = (unsigned)i0 * (unsigned)ny + (unsigned)jl;

#pragma unroll
    for (int r = 0; r < 4; r++) {
        const int i = i0 + r;
        const float uC = uc[r + 1], vC = vc[r + 1];

        // y-stencil values via warp shuffle (all lanes participate uniformly)
        float uy0 = __shfl_up_sync(FULLMASK, uC, 1);
        float uy2 = __shfl_down_sync(FULLMASK, uC, 1);
        float vy0 = __shfl_up_sync(FULLMASK, vC, 1);
        float vy2 = __shfl_down_sync(FULLMASK, vC, 1);
        float uy1 = uC, vy1 = vC;
        if (yedge) {
            // one-sided boundary triple: read directly (2 lanes of edge blocks)
            int jc = (j == 0) ? 1 : (ny - 2);
            unsigned b = (unsigned)i * (unsigned)ny + (unsigned)jc;
            uy0 = __ldg(u + b - 1); uy1 = __ldg(u + b); uy2 = __ldg(u + b + 1);
            vy0 = __ldg(v + b - 1); vy1 = __ldg(v + b); vy2 = __ldg(v + b + 1);
        }

        // x-stencil values from the register column (clamped center at i edges)
        float ux0, ux1, ux2, vx0, vx1, vx2;
        if (r == 0 && i == 0) {
            ux0 = uc[1]; ux1 = uc[2]; ux2 = uc[3];
            vx0 = vc[1]; vx1 = vc[2]; vx2 = vc[3];
        } else if (r == 3 && i == nx - 1) {
            ux0 = uc[2]; ux1 = uc[3]; ux2 = uc[4];
            vx0 = vc[2]; vx1 = vc[3]; vx2 = vc[4];
        } else {
            ux0 = uc[r]; ux1 = uc[r + 1]; ux2 = uc[r + 2];
            vx0 = vc[r]; vx1 = vc[r + 1]; vx2 = vc[r + 2];
        }

        const float4 cxa = g_cxA[i];   // warp-uniform broadcast
        const float2 cxb = g_cxB[i];

        float d1y_u = cya.x * uy0 + cya.y * uy1 + cya.z * uy2;
        float d2y_u = cya.w * uy0 + cyb.x * uy1 + cyb.y * uy2;
        float d1y_v = cya.x * vy0 + cya.y * vy1 + cya.z * vy2;
        float d2y_v = cya.w * vy0 + cyb.x * vy1 + cyb.y * vy2;

        float d1x_u = cxa.x * ux0 + cxa.y * ux1 + cxa.z * ux2;
        float d2x_u = cxa.w * ux0 + cxb.x * ux1 + cxb.y * ux2;
        float d1x_v = cxa.x * vx0 + cxa.y * vx1 + cxa.z * vx2;
        float d2x_v = cxa.w * vx0 + cxb.x * vx1 + cxb.y * vx2;

        float du = mu * (d2y_u + d2x_u) - uC * d1x_u - vC * d1y_u + 0.01f;
        float dv = mu * (d2y_v + d2x_v) - uC * d1x_v - vC * d1y_v;

        if (j == 0 || j == ny - 1 || i == 0) du = 0.f;
        if (j == 0 || i == 0) dv = 0.f;

        if (compute && i < nx) {
            unsigned o = obase + (unsigned)r * (unsigned)ny;
            out[o] = du;
            out[plane + o] = dv;
        }
    }
}

extern "C" void kernel_launch(void* const* d_in, const int* in_sizes, int n_in,
                              void* d_out, int out_size) {
    const float* state = (const float*)d_in[1];
    const float* x = (const float*)d_in[2];
    const float* y = (const float*)d_in[3];
    const float* mu = (const float*)d_in[4];
    int nx = in_sizes[2];
    int ny = in_sizes[3];
    float* out = (float*)d_out;

    int nmax = nx > ny ? nx : ny;
    coeff_kernel<<<(nmax + 255) / 256, 256>>>(x, nx, y, ny);

    dim3 block(32, 8);                       // warp = 30 output columns, 32 i-rows/block
    dim3 grid((ny + 29) / 30, (nx + 31) / 32);
    rhs_kernel<<<grid, block>>>(state, mu, out, nx, ny);
}

// round 6
// speedup vs baseline: 1.6281x; 1.1763x over previous
#include <cuda_runtime.h>
#include <cuda_bf16.h>

// RHS of 2-field Burgers-like PDE on nonuniform 2048x4096 grid.
// Inputs (metadata order): t[1], state[2*NX*NY], x[NX], y[NY], mu[1]
// Output: [2, NX, NY] float32.

#define NX_MAX 2048
#define NY_MAX 4096
#define FULLMASK 0xffffffffu

// x-direction coefficients: AoS (warp-uniform broadcast loads)
__device__ float4 g_cxA[NX_MAX];   // (d1a, d1b, d1c, d2a)
__device__ float2 g_cxB[NX_MAX];   // (d2b, d2c)
// y-direction coefficients: SoA, 16B-aligned for float4 loads
__device__ __align__(16) float g_cy1a[NY_MAX];
__device__ __align__(16) float g_cy1b[NY_MAX];
__device__ __align__(16) float g_cy1c[NY_MAX];
__device__ __align__(16) float g_cy2a[NY_MAX];
__device__ __align__(16) float g_cy2b[NY_MAX];
__device__ __align__(16) float g_cy2c[NY_MAX];

__device__ __forceinline__ void stencil_coeffs(const float* __restrict__ g,
                                               int n, int k, float* c) {
    if (k == 0) {
        float hA = g[1] - g[0], hB = g[2] - g[1];
        c[0] = -(2.f * hA + hB) / (hA * (hA + hB));
        c[1] = (hA + hB) / (hA * hB);
        c[2] = -hA / (hB * (hA + hB));
        c[3] = 2.f / (hA * (hA + hB));
        c[4] = -2.f / (hA * hB);
        c[5] = 2.f / (hB * (hA + hB));
    } else if (k == n - 1) {
        float hC = g[n - 2] - g[n - 3], hD = g[n - 1] - g[n - 2];
        c[0] = hD / (hC * (hC + hD));
        c[1] = -(hC + hD) / (hC * hD);
        c[2] = (hC + 2.f * hD) / (hD * (hC + hD));
        c[3] = 2.f / (hC * (hC + hD));
        c[4] = -2.f / (hC * hD);
        c[5] = 2.f / (hD * (hC + hD));
    } else {
        float h1 = g[k] - g[k - 1], h2 = g[k + 1] - g[k];
        c[0] = -h2 / (h1 * (h1 + h2));
        c[1] = (h2 - h1) / (h1 * h2);
        c[2] = h1 / (h2 * (h1 + h2));
        c[3] = 2.f / (h1 * (h1 + h2));
        c[4] = -2.f / (h1 * h2);
        c[5] = 2.f / (h2 * (h1 + h2));
    }
}

__global__ __launch_bounds__(256)
void coeff_kernel(const float* __restrict__ x, int nx,
                  const float* __restrict__ y, int ny) {
    int k = blockIdx.x * blockDim.x + threadIdx.x;
    float c[6];
    if (k < nx) {
        stencil_coeffs(x, nx, k, c);
        g_cxA[k] = make_float4(c[0], c[1], c[2], c[3]);
        g_cxB[k] = make_float2(c[4], c[5]);
    }
    if (k < ny) {
        stencil_coeffs(y, ny, k, c);
        g_cy1a[k] = c[0]; g_cy1b[k] = c[1]; g_cy1c[k] = c[2];
        g_cy2a[k] = c[3]; g_cy2b[k] = c[4]; g_cy2c[k] = c[5];
    }
}

__device__ __forceinline__ float4 ld4(const float* p) {
    return *reinterpret_cast<const float4*>(p);
}
__device__ __forceinline__ void st4(float* p, float4 v) {
    *reinterpret_cast<float4*>(p) = v;
}

// Warp owns 128 aligned columns [base, base+128); lane owns 4 (float4).
// Each thread computes 4 consecutive i-rows from a 6-row register column.
__global__ __launch_bounds__(256)
void rhs_kernel(const float* __restrict__ state,
                const float* __restrict__ mu_p,
                float* __restrict__ out, int nx, int ny) {
    const int lane = threadIdx.x;
    const int base = blockIdx.x * 128;
    const int j0 = base + lane * 4;
    if (j0 >= ny) return;
    const int i0 = (blockIdx.y * blockDim.y + threadIdx.y) * 4;
    const unsigned plane = (unsigned)nx * (unsigned)ny;
    const float* __restrict__ u = state;
    const float* __restrict__ v = state + plane;
    const float mu = mu_p[0];

    // 6-row float4 column (rows i0-1 .. i0+4, i-clamped)
    float4 uc[6], vc[6];
#pragma unroll
    for (int k = 0; k < 6; k++) {
        int ir = min(max(i0 - 1 + k, 0), nx - 1);
        unsigned off = (unsigned)ir * (unsigned)ny + (unsigned)j0;
        uc[k] = ld4(u + off);
        vc[k] = ld4(v + off);
    }

    // Halo columns (warp-edge neighbors), compute rows only.
    float hu[4] = {0, 0, 0, 0}, hv[4] = {0, 0, 0, 0};
    const bool is_halo = (lane == 0) || (lane == 31);
    if (is_halo) {
        int jh = (lane == 0) ? max(base - 1, 0) : min(base + 128, ny - 1);
#pragma unroll
        for (int r = 0; r < 4; r++) {
            unsigned off = (unsigned)(i0 + r) * (unsigned)ny + (unsigned)jh;
            hu[r] = __ldg(u + off);
            hv[r] = __ldg(v + off);
        }
    }

    // y-coefficients for this lane's 4 columns (one-sided embedded at edges)
    const float4 c1a = ld4(&g_cy1a[j0]);
    const float4 c1b = ld4(&g_cy1b[j0]);
    const float4 c1c = ld4(&g_cy1c[j0]);
    const float4 c2a = ld4(&g_cy2a[j0]);
    const float4 c2b = ld4(&g_cy2b[j0]);
    const float4 c2c = ld4(&g_cy2c[j0]);

    const bool e0b = (j0 == 0);            // column .x is the global left edge
    const bool e3b = (j0 + 3 == ny - 1);   // column .w is the global right edge
    const unsigned obase = (unsigned)i0 * (unsigned)ny + (unsigned)j0;

#pragma unroll
    for (int r = 0; r < 4; r++) {
        const int i = i0 + r;
        const float4 U = uc[r + 1], V = vc[r + 1];

        // Warp-edge neighbors via shuffle; lanes 0/31 patch from halo loads.
        float lu = __shfl_up_sync(FULLMASK, U.w, 1);
        float ru = __shfl_down_sync(FULLMASK, U.x, 1);
        float lv = __shfl_up_sync(FULLMASK, V.w, 1);
        float rv = __shfl_down_sync(FULLMASK, V.x, 1);
        if (lane == 0)  { lu = hu[r]; lv = hv[r]; }
        if (lane == 31) { ru = hu[r]; rv = hv[r]; }

        // Per-element y-stencil triples. At j==0 the one-sided stencil reads
        // columns {0,1,2} = (.x,.y,.z); at j==ny-1 it reads (.y,.z,.w).
        float a0u = e0b ? U.x : lu,  b0u = e0b ? U.y : U.x, g0u = e0b ? U.z : U.y;
        float a0v = e0b ? V.x : lv,  b0v = e0b ? V.y : V.x, g0v = e0b ? V.z : V.y;
        float a3u = e3b ? U.y : U.z, b3u = e3b ? U.z : U.w, g3u = e3b ? U.w : ru;
        float a3v = e3b ? V.y : V.z, b3v = e3b ? V.z : V.w, g3v = e3b ? V.w : rv;

        float4 d1y_u, d2y_u, d1y_v, d2y_v;
        d1y_u.x = c1a.x * a0u + c1b.x * b0u + c1c.x * g0u;
        d2y_u.x = c2a.x * a0u + c2b.x * b0u + c2c.x * g0u;
        d1y_v.x = c1a.x * a0v + c1b.x * b0v + c1c.x * g0v;
        d2y_v.x = c2a.x * a0v + c2b.x * b0v + c2c.x * g0v;

        d1y_u.y = c1a.y * U.x + c1b.y * U.y + c1c.y * U.z;
        d2y_u.y = c2a.y * U.x + c2b.y * U.y + c2c.y * U.z;
        d1y_v.y = c1a.y * V.x + c1b.y * V.y + c1c.y * V.z;
        d2y_v.y = c2a.y * V.x + c2b.y * V.y + c2c.y * V.z;

        d1y_u.z = c1a.z * U.y + c1b.z * U.z + c1c.z * U.w;
        d2y_u.z = c2a.z * U.y + c2b.z * U.z + c2c.z * U.w;
        d1y_v.z = c1a.z * V.y + c1b.z * V.z + c1c.z * V.w;
        d2y_v.z = c2a.z * V.y + c2b.z * V.z + c2c.z * V.w;

        d1y_u.w = c1a.w * a3u + c1b.w * b3u + c1c.w * g3u;
        d2y_u.w = c2a.w * a3u + c2b.w * b3u + c2c.w * g3u;
        d1y_v.w = c1a.w * a3v + c1b.w * b3v + c1c.w * g3v;
        d2y_v.w = c2a.w * a3v + c2b.w * b3v + c2c.w * g3v;

        // x-stencil triples from register column (clamped center at i edges)
        float4 X0, X1, X2, Y0, Y1, Y2;
        if (r == 0 && i == 0) {
            X0 = uc[1]; X1 = uc[2]; X2 = uc[3];
            Y0 = vc[1]; Y1 = vc[2]; Y2 = vc[3];
        } else if (r == 3 && i == nx - 1) {
            X0 = uc[2]; X1 = uc[3]; X2 = uc[4];
            Y0 = vc[2]; Y1 = vc[3]; Y2 = vc[4];
        } else {
            X0 = uc[r]; X1 = uc[r + 1]; X2 = uc[r + 2];
            Y0 = vc[r]; Y1 = vc[r + 1]; Y2 = vc[r + 2];
        }

        const float4 cxa = g_cxA[i];   // warp-uniform
        const float2 cxb = g_cxB[i];

        float4 du, dv;
        {
            float d1x, d2x, d1xv, d2xv;
#define DO_ELEM(E) \
            d1x  = cxa.x * X0.E + cxa.y * X1.E + cxa.z * X2.E;            \
            d2x  = cxa.w * X0.E + cxb.x * X1.E + cxb.y * X2.E;            \
            d1xv = cxa.x * Y0.E + cxa.y * Y1.E + cxa.z * Y2.E;            \
            d2xv = cxa.w * Y0.E + cxb.x * Y1.E + cxb.y * Y2.E;            \
            du.E = mu * (d2y_u.E + d2x) - U.E * d1x - V.E * d1y_u.E + 0.01f; \
            dv.E = mu * (d2y_v.E + d2xv) - U.E * d1xv - V.E * d1y_v.E;
            DO_ELEM(x) DO_ELEM(y) DO_ELEM(z) DO_ELEM(w)
#undef DO_ELEM
        }

        // Boundary zeroing per reference
        if (i == 0) { du = make_float4(0.f, 0.f, 0.f, 0.f);
                      dv = make_float4(0.f, 0.f, 0.f, 0.f); }
        if (e0b) { du.x = 0.f; dv.x = 0.f; }
        if (e3b) { du.w = 0.f; }

        unsigned o = obase + (unsigned)r * (unsigned)ny;
        st4(out + o, du);
        st4(out + plane + o, dv);
    }
}

extern "C" void kernel_launch(void* const* d_in, const int* in_sizes, int n_in,
                              void* d_out, int out_size) {
    const float* state = (const float*)d_in[1];
    const float* x = (const float*)d_in[2];
    const float* y = (const float*)d_in[3];
    const float* mu = (const float*)d_in[4];
    int nx = in_sizes[2];
    int ny = in_sizes[3];
    float* out = (float*)d_out;

    int nmax = nx > ny ? nx : ny;
    coeff_kernel<<<(nmax + 255) / 256, 256>>>(x, nx, y, ny);

    dim3 block(32, 8);                        // warp = 128 columns, 32 i-rows/block
    dim3 grid((ny + 127) / 128, (nx + 31) / 32);
    rhs_kernel<<<grid, block>>>(state, mu, out, nx, ny);
}